// round 1
// baseline (speedup 1.0000x reference)
#include <cuda_runtime.h>

#define BATCH 32
#define D_IN  1024
#define D_OUT 1024
#define E_DIM (D_OUT + 2 * D_IN + 4)   // 3076

// Scratch (allocation-free rule: __device__ globals)
__device__ float g_out [BATCH * E_DIM];   // first matvec result
__device__ float g_kphi[BATCH * D_IN];    // softmax(k)
__device__ float g_qphi[BATCH * D_IN];    // softmax(q)
__device__ float g_sig [BATCH * 4];       // sigmoid(b1..b4)

// ---------------------------------------------------------------------------
// Kernel 1: out[b,e] = dot(w[b,e,:], x[b,:]); also writes y = out[:, :D_OUT].
// One warp per row e; 8 warps/block; x staged in shared.
// ---------------------------------------------------------------------------
__global__ void __launch_bounds__(256) srwm_matvec(const float* __restrict__ w,
                                                   const float* __restrict__ x,
                                                   float* __restrict__ y_out,
                                                   int write_y)
{
    __shared__ float4 sx4[D_IN / 4];
    const int b = blockIdx.y;

    const float4* x4 = (const float4*)(x + (size_t)b * D_IN);
    for (int i = threadIdx.x; i < D_IN / 4; i += blockDim.x) sx4[i] = x4[i];
    __syncthreads();

    const int warp = threadIdx.x >> 5;
    const int lane = threadIdx.x & 31;
    const int e = blockIdx.x * 8 + warp;
    if (e >= E_DIM) return;

    const float4* wrow = (const float4*)(w + ((size_t)b * E_DIM + e) * D_IN);

    float acc = 0.0f;
#pragma unroll
    for (int j = 0; j < 8; j++) {
        float4 wv = wrow[lane + j * 32];
        float4 xv = sx4[lane + j * 32];
        acc += wv.x * xv.x + wv.y * xv.y + wv.z * xv.z + wv.w * xv.w;
    }
#pragma unroll
    for (int off = 16; off; off >>= 1)
        acc += __shfl_xor_sync(0xffffffffu, acc, off);

    if (lane == 0) {
        g_out[(size_t)b * E_DIM + e] = acc;
        if (write_y && e < D_OUT) y_out[(size_t)b * D_OUT + e] = acc;
    }
}

// ---------------------------------------------------------------------------
// Kernel 2: per-batch softmax of k and q rows, plus 4 sigmoids. 32 blocks.
// ---------------------------------------------------------------------------
__global__ void __launch_bounds__(256) srwm_softmax()
{
    const int b    = blockIdx.x;
    const int tid  = threadIdx.x;
    const int lane = tid & 31;
    const int warp = tid >> 5;

    __shared__ float sred[8];
    __shared__ float sval;

    const float* base = g_out + (size_t)b * E_DIM;

    // ---- K softmax ----
    {
        float4 v = ((const float4*)(base + D_OUT))[tid];
        float m = fmaxf(fmaxf(v.x, v.y), fmaxf(v.z, v.w));
#pragma unroll
        for (int off = 16; off; off >>= 1)
            m = fmaxf(m, __shfl_xor_sync(0xffffffffu, m, off));
        if (lane == 0) sred[warp] = m;
        __syncthreads();
        if (tid == 0) {
            float t = sred[0];
#pragma unroll
            for (int i = 1; i < 8; i++) t = fmaxf(t, sred[i]);
            sval = t;
        }
        __syncthreads();
        m = sval;
        float e0 = __expf(v.x - m), e1 = __expf(v.y - m);
        float e2 = __expf(v.z - m), e3 = __expf(v.w - m);
        float s = e0 + e1 + e2 + e3;
#pragma unroll
        for (int off = 16; off; off >>= 1)
            s += __shfl_xor_sync(0xffffffffu, s, off);
        __syncthreads();
        if (lane == 0) sred[warp] = s;
        __syncthreads();
        if (tid == 0) {
            float t = 0.0f;
#pragma unroll
            for (int i = 0; i < 8; i++) t += sred[i];
            sval = t;
        }
        __syncthreads();
        float inv = 1.0f / sval;
        float4 o = {e0 * inv, e1 * inv, e2 * inv, e3 * inv};
        ((float4*)(g_kphi + (size_t)b * D_IN))[tid] = o;
        __syncthreads();
    }

    // ---- Q softmax ----
    {
        float4 v = ((const float4*)(base + D_OUT + D_IN))[tid];
        float m = fmaxf(fmaxf(v.x, v.y), fmaxf(v.z, v.w));
#pragma unroll
        for (int off = 16; off; off >>= 1)
            m = fmaxf(m, __shfl_xor_sync(0xffffffffu, m, off));
        if (lane == 0) sred[warp] = m;
        __syncthreads();
        if (tid == 0) {
            float t = sred[0];
#pragma unroll
            for (int i = 1; i < 8; i++) t = fmaxf(t, sred[i]);
            sval = t;
        }
        __syncthreads();
        m = sval;
        float e0 = __expf(v.x - m), e1 = __expf(v.y - m);
        float e2 = __expf(v.z - m), e3 = __expf(v.w - m);
        float s = e0 + e1 + e2 + e3;
#pragma unroll
        for (int off = 16; off; off >>= 1)
            s += __shfl_xor_sync(0xffffffffu, s, off);
        __syncthreads();
        if (lane == 0) sred[warp] = s;
        __syncthreads();
        if (tid == 0) {
            float t = 0.0f;
#pragma unroll
            for (int i = 0; i < 8; i++) t += sred[i];
            sval = t;
        }
        __syncthreads();
        float inv = 1.0f / sval;
        float4 o = {e0 * inv, e1 * inv, e2 * inv, e3 * inv};
        ((float4*)(g_qphi + (size_t)b * D_IN))[tid] = o;
    }

    // ---- sigmoids of the 4 bias outputs ----
    if (tid < 4) {
        float v = base[D_OUT + 2 * D_IN + tid];
        g_sig[b * 4 + tid] = 1.0f / (1.0f + __expf(-v));
    }
}

// ---------------------------------------------------------------------------
// Kernel 3: fused vbar/v matvecs + rank-1 update.
// Per row e: load w row once into registers, compute vbar = row.kphi and
// v = row.qphi, then write w_out = row + sig*(v-vbar)*kphi.
// 8 warps/block, each warp does 4 rows; kphi/qphi staged in shared.
// ---------------------------------------------------------------------------
__global__ void __launch_bounds__(256) srwm_update(const float* __restrict__ w,
                                                   float* __restrict__ wout)
{
    __shared__ float4 sk4[D_IN / 4];
    __shared__ float4 sq4[D_IN / 4];
    __shared__ float  ssig[4];

    const int b = blockIdx.y;

    const float4* gk = (const float4*)(g_kphi + (size_t)b * D_IN);
    const float4* gq = (const float4*)(g_qphi + (size_t)b * D_IN);
    for (int i = threadIdx.x; i < D_IN / 4; i += blockDim.x) {
        sk4[i] = gk[i];
        sq4[i] = gq[i];
    }
    if (threadIdx.x < 4) ssig[threadIdx.x] = g_sig[b * 4 + threadIdx.x];
    __syncthreads();

    const int warp = threadIdx.x >> 5;
    const int lane = threadIdx.x & 31;
    const int e_base = blockIdx.x * 32 + warp * 4;

#pragma unroll 1
    for (int r = 0; r < 4; r++) {
        const int e = e_base + r;
        if (e >= E_DIM) break;

        const float4* wrow = (const float4*)(w    + ((size_t)b * E_DIM + e) * D_IN);
        float4*       orow = (float4*)      (wout + ((size_t)b * E_DIM + e) * D_IN);

        float4 wv[8];
        float acc_v = 0.0f, acc_vb = 0.0f;
#pragma unroll
        for (int j = 0; j < 8; j++) {
            wv[j] = wrow[lane + j * 32];
            float4 kv = sk4[lane + j * 32];
            float4 qv = sq4[lane + j * 32];
            acc_vb += wv[j].x * kv.x + wv[j].y * kv.y + wv[j].z * kv.z + wv[j].w * kv.w;
            acc_v  += wv[j].x * qv.x + wv[j].y * qv.y + wv[j].z * qv.z + wv[j].w * qv.w;
        }
#pragma unroll
        for (int off = 16; off; off >>= 1) {
            acc_v  += __shfl_xor_sync(0xffffffffu, acc_v,  off);
            acc_vb += __shfl_xor_sync(0xffffffffu, acc_vb, off);
        }

        const int seg = (e < D_OUT) ? 0 : (e < D_OUT + D_IN) ? 1 : (e < D_OUT + 2 * D_IN) ? 2 : 3;
        const float coeff = ssig[seg] * (acc_v - acc_vb);

#pragma unroll
        for (int j = 0; j < 8; j++) {
            float4 kv = sk4[lane + j * 32];
            float4 o;
            o.x = wv[j].x + coeff * kv.x;
            o.y = wv[j].y + coeff * kv.y;
            o.z = wv[j].z + coeff * kv.z;
            o.w = wv[j].w + coeff * kv.w;
            orow[lane + j * 32] = o;
        }
    }
}

// ---------------------------------------------------------------------------
// kernel_launch
// ---------------------------------------------------------------------------
extern "C" void kernel_launch(void* const* d_in, const int* in_sizes, int n_in,
                              void* d_out, int out_size)
{
    // Inputs: x (BATCH*D_IN) then w (BATCH*E_DIM*D_IN); swap defensively.
    const float* x = (const float*)d_in[0];
    const float* w = (const float*)d_in[1];
    if (n_in >= 2 && in_sizes[0] != BATCH * D_IN) {
        x = (const float*)d_in[1];
        w = (const float*)d_in[0];
    }

    const size_t wout_elems = (size_t)BATCH * E_DIM * D_IN;
    float* out = (float*)d_out;

    // Output packing: y (BATCH*D_OUT) followed by w_out (BATCH*E_DIM*D_IN).
    float* y_ptr = out;
    float* wout_ptr = out + ((size_t)out_size - wout_elems);
    const int write_y = ((size_t)out_size > wout_elems) ? 1 : 0;

    dim3 grid1((E_DIM + 7) / 8, BATCH);
    srwm_matvec<<<grid1, 256>>>(w, x, y_ptr, write_y);

    srwm_softmax<<<BATCH, 256>>>();

    dim3 grid3((E_DIM + 31) / 32, BATCH);
    srwm_update<<<grid3, 256>>>(w, wout_ptr);
}